// round 15
// baseline (speedup 1.0000x reference)
#include <cuda_runtime.h>
#include <cuda_bf16.h>
#include <cstdint>

#define NPTS 4096
#define DIMS 1024
#define NCLS 64
#define EPSV 0.1f

#define RCH  32                 // row chunks for phase-1 partials
#define RPC  (NPTS / RCH)       // 128 rows per chunk
#define DCH  64                 // dims per phase-1 block
#define NDCH (DIMS / DCH)       // 16

// k_main tiling (bf16 mma.sync m16n8k16)
#define BM   256
#define BN   128
#define BK   64                 // bf16 elems per chunk = 128 B per row
#define NCH  (DIMS / BK)        // 16 chunks
#define NTILES 272              // triangle tiles: sum_{bi<16} (32 - 2*bi)
#define LSTRH 72                // smem row stride in halfs (144 B)
#define A_BYTES (BM * LSTRH * 2)   // 36864
#define B_BYTES (BN * LSTRH * 2)   // 18432
#define STGB  (A_BYTES + B_BYTES)  // 55296 B per stage
#define NSTG  4
#define DSMEM_BYTES (NSTG * STGB)  // 221184 B

// ---- static device scratch (no allocations allowed) ----
__device__ int      g_counts[NCLS];
__device__ float    g_spart[DIMS][RCH][NCLS];   // 8 MB partials, contiguous per dim
__device__ float    g_Apart[RCH][DIMS];
__device__ float    g_Qpart[RCH][DIMS];
__device__ float    g_s[NCLS][DIMS];
__device__ float    g_w[DIMS];
__device__ unsigned short g_xh[(size_t)NPTS * DIMS];   // bf16(x)
__device__ unsigned short g_xwh[(size_t)NPTS * DIMS];  // bf16(w*x)
__device__ float    g_sq[NPTS];                 // sq_i = sum_d w_d x_id^2 (fp32 exact)
__device__ float    g_P[NCLS];
__device__ float    g_wss[NCLS];
__device__ double   g_pairsum;
__device__ int      g_done;

// ---------------- helpers ----------------
__device__ __forceinline__ uint32_t smem_u32(const void* p) {
    uint32_t a;
    asm("{ .reg .u64 t; cvta.to.shared.u64 t, %1; cvt.u32.u64 %0, t; }" : "=r"(a) : "l"(p));
    return a;
}
__device__ __forceinline__ void cp16(uint32_t dst, const void* src) {
    asm volatile("cp.async.cg.shared.global [%0], [%1], 16;" :: "r"(dst), "l"(src) : "memory");
}
__device__ __forceinline__ void ldm_x4(uint32_t& r0, uint32_t& r1, uint32_t& r2, uint32_t& r3,
                                       uint32_t addr) {
    asm volatile("ldmatrix.sync.aligned.m8n8.x4.shared.b16 {%0,%1,%2,%3}, [%4];"
                 : "=r"(r0), "=r"(r1), "=r"(r2), "=r"(r3) : "r"(addr));
}
__device__ __forceinline__ void mma_bf16(float* c, uint32_t a0, uint32_t a1, uint32_t a2,
                                         uint32_t a3, uint32_t b0, uint32_t b1) {
    asm volatile("mma.sync.aligned.m16n8k16.row.col.f32.bf16.bf16.f32 "
                 "{%0,%1,%2,%3}, {%4,%5,%6,%7}, {%8,%9}, {%0,%1,%2,%3};"
                 : "+f"(c[0]), "+f"(c[1]), "+f"(c[2]), "+f"(c[3])
                 : "r"(a0), "r"(a1), "r"(a2), "r"(a3), "r"(b0), "r"(b1));
}

// ------------------------------------------------------------------
// Fused init + class histogram (single block).
__global__ void k_init(const int* __restrict__ tgt) {
    __shared__ int hist[NCLS];
    int t = threadIdx.x;                 // 1024 threads
    if (t < NCLS) { hist[t] = 0; g_P[t] = 0.f; g_wss[t] = 0.f; }
    if (t == NCLS) { g_pairsum = 0.0; g_done = 0; }
    __syncthreads();
    #pragma unroll
    for (int i = t; i < NPTS; i += 1024) atomicAdd(&hist[tgt[i]], 1);
    __syncthreads();
    if (t < NCLS) g_counts[t] = hist[t];
}

__global__ void k_phase1(const float* __restrict__ X, const int* __restrict__ tgt) {
    __shared__ float s_sh[NCLS * DCH];
    __shared__ float cnt_sh[NCLS];
    __shared__ int   tg_sh[RPC];
    int t  = threadIdx.x;                // 0..63
    int dc = blockIdx.x, rc = blockIdx.y;

    for (int i = t; i < NCLS * DCH; i += 64) s_sh[i] = 0.f;
    cnt_sh[t] = (float)g_counts[t];
    for (int r = t; r < RPC; r += 64) tg_sh[r] = tgt[rc * RPC + r];
    __syncthreads();

    const float* xp = X + (size_t)(rc * RPC) * DIMS + dc * DCH + t;
    float aacc = 0.f, qacc = 0.f;
    #pragma unroll 8
    for (int r = 0; r < RPC; r++) {
        float v = xp[(size_t)r * DIMS];
        int   k = tg_sh[r];
        s_sh[k * DCH + t] += v;
        float v2 = v * v;
        qacc += v2;
        aacc = fmaf(cnt_sh[k], v2, aacc);
    }
    __syncthreads();

    int d = dc * DCH + t;
    #pragma unroll
    for (int k4 = 0; k4 < NCLS; k4 += 4) {
        float4 v = make_float4(s_sh[(k4 + 0) * DCH + t], s_sh[(k4 + 1) * DCH + t],
                               s_sh[(k4 + 2) * DCH + t], s_sh[(k4 + 3) * DCH + t]);
        *(float4*)&g_spart[d][rc][k4] = v;
    }
    g_Apart[rc][d] = aacc;
    g_Qpart[rc][d] = qacc;
}

// 256 threads: block d streams its contiguous 8KB partial slab, computes w_d,
// and folds the wss contribution (atomicAdd per class).
__global__ void k_reduce_w() {
    int d = blockIdx.x, t = threadIdx.x;
    int k = t & 63, rg = t >> 6;         // class, rc-group (4 groups x 8 rc)

    float s = 0.f;
    #pragma unroll
    for (int rc = rg * 8; rc < rg * 8 + 8; rc++) s += g_spart[d][rc][k];
    __shared__ float sp[4][NCLS];
    sp[rg][k] = s;
    __syncthreads();

    __shared__ float sh1[NCLS], sh2[NCLS], sh3[NCLS], sh4[NCLS], sh5[NCLS];
    __shared__ float s_k[NCLS];
    __shared__ float s_wd;
    if (rg == 0) {
        s = sp[0][k] + sp[1][k] + sp[2][k] + sp[3][k];
        g_s[k][d] = s;
        s_k[k] = s;
        float c = (float)g_counts[k];
        sh1[k] = s * s; sh2[k] = s; sh3[k] = c * c;
        sh4[k] = (k < RCH) ? g_Apart[k][d] : 0.f;   // thread k doubles as rc=k
        sh5[k] = (k < RCH) ? g_Qpart[k][d] : 0.f;
    }
    __syncthreads();
    for (int off = 32; off > 0; off >>= 1) {
        if (t < off) {
            sh1[t] += sh1[t + off]; sh2[t] += sh2[t + off]; sh3[t] += sh3[t + off];
            sh4[t] += sh4[t + off]; sh5[t] += sh5[t + off];
        }
        __syncthreads();
    }

    if (t == 0) {
        float ssum2 = sh1[0], stot = sh2[0], sumc2 = sh3[0];
        float a = sh4[0], q = sh5[0];
        float cntpos = sumc2 - (float)NPTS;
        float cntneg = (float)NPTS * (float)NPTS - sumc2;
        float sum_pos = 2.f * a - 2.f * ssum2;
        float sum_neg = 2.f * (float)NPTS * q - 2.f * a - 2.f * stot * stot + 2.f * ssum2;
        s_wd = cntneg / (sum_neg + EPSV) - cntpos / (sum_pos + EPSV);
        g_w[d] = s_wd;
    }
    __syncthreads();
    if (t < NCLS) {                      // fused wss: wss_k += w_d * s_kd^2
        float s0 = s_k[t];
        atomicAdd(&g_wss[t], s_wd * s0 * s0);
    }
}

// xh = bf16(x), xwh = bf16(w*x), sq_i = sum w x^2 (fp32), P_k += sq_i
__global__ void k_xwsq(const float* __restrict__ X, const int* __restrict__ tgt) {
    int i = blockIdx.x, t = threadIdx.x;   // 256 threads, 4 dims each
    const float4* xr = (const float4*)(X + (size_t)i * DIMS);
    const float4* wr = (const float4*)g_w;
    float4 x4 = xr[t], w4 = wr[t], o;
    o.x = x4.x * w4.x; o.y = x4.y * w4.y; o.z = x4.z * w4.z; o.w = x4.w * w4.w;
    float acc = x4.x * o.x + x4.y * o.y + x4.z * o.z + x4.w * o.w;

    __nv_bfloat162 hx0 = __floats2bfloat162_rn(x4.x, x4.y);
    __nv_bfloat162 hx1 = __floats2bfloat162_rn(x4.z, x4.w);
    __nv_bfloat162 ho0 = __floats2bfloat162_rn(o.x, o.y);
    __nv_bfloat162 ho1 = __floats2bfloat162_rn(o.z, o.w);
    uint2* dxh  = (uint2*)(g_xh  + (size_t)i * DIMS);
    uint2* dxwh = (uint2*)(g_xwh + (size_t)i * DIMS);
    uint2 px, po;
    px.x = *(uint32_t*)&hx0; px.y = *(uint32_t*)&hx1;
    po.x = *(uint32_t*)&ho0; po.y = *(uint32_t*)&ho1;
    dxh[t] = px; dxwh[t] = po;

    __shared__ float red[256];
    red[t] = acc; __syncthreads();
    for (int off = 128; off > 0; off >>= 1) { if (t < off) red[t] += red[t + off]; __syncthreads(); }
    if (t == 0) { g_sq[i] = red[0]; atomicAdd(&g_P[tgt[i]], red[0]); }
}

// ------------------------------------------------------------------
// bf16 mma.sync fused Gram + softplus. 256x128 tile, BK=64, 4-stage cp.async
// (one __syncthreads per chunk), ldmatrix.x4 fragments, 8 warps (4m x 2n).
// Last finishing block computes the final loss (fence + done-counter).
__device__ __forceinline__ void load_stage(uint32_t sA, uint32_t sB,
                                           const unsigned short* Ag,
                                           const unsigned short* Bg,
                                           int kt, int t) {
    int seg = t & 7;               // 16B segment within 128B row
    int r0  = t >> 3;              // 32 rows per pass
    #pragma unroll
    for (int p = 0; p < 8; p++) {  // A: 256 rows
        int row = r0 + 32 * p;
        cp16(sA + row * 144u + seg * 16u, Ag + (size_t)row * DIMS + kt + seg * 8);
    }
    #pragma unroll
    for (int p = 0; p < 4; p++) {  // B: 128 rows
        int row = r0 + 32 * p;
        cp16(sB + row * 144u + seg * 16u, Bg + (size_t)row * DIMS + kt + seg * 8);
    }
    asm volatile("cp.async.commit_group;" ::: "memory");
}

__global__ void __launch_bounds__(256) k_main(float* __restrict__ out) {
    // map linear block id -> (bi, bj) on the triangle bj >= 2*bi
    int L = blockIdx.x, bi = 0, cnt = 32;
    while (L >= cnt) { L -= cnt; bi++; cnt -= 2; }
    int bj = 2 * bi + L;
    int iBase = bi * BM, jBase = bj * BN;

    extern __shared__ char dsmem[];
    __shared__ float red[256];
    __shared__ float sqi_sh[BM];
    __shared__ float sqj_sh[BN];

    int t = threadIdx.x;
    int lane = t & 31, w = t >> 5;
    int warpRow = w & 3, warpCol = w >> 2;    // 4 x 2 warps
    uint32_t sbase = smem_u32(dsmem);

    const unsigned short* Ag = g_xh  + (size_t)iBase * DIMS;
    const unsigned short* Bg = g_xwh + (size_t)jBase * DIMS;

    // prefetch sq rows/cols for the epilogue
    sqi_sh[t] = g_sq[iBase + t];
    if (t < BN) sqj_sh[t] = g_sq[jBase + t];

    float acc[4][8][4];
    #pragma unroll
    for (int mf = 0; mf < 4; mf++)
        #pragma unroll
        for (int nf = 0; nf < 8; nf++)
            #pragma unroll
            for (int q = 0; q < 4; q++) acc[mf][nf][q] = 0.f;

    // prologue: chunks 0..2 into stages 0..2
    load_stage(sbase,            sbase + A_BYTES,            Ag, Bg, 0,      t);
    load_stage(sbase + STGB,     sbase + STGB + A_BYTES,     Ag, Bg, BK,     t);
    load_stage(sbase + 2 * STGB, sbase + 2 * STGB + A_BYTES, Ag, Bg, 2 * BK, t);

    // precomputed fragment address components
    uint32_t aRow = (uint32_t)(warpRow * 64 + (lane & 15));
    uint32_t aKof = (uint32_t)((lane >> 4) * 16);
    int grp = lane >> 3;
    uint32_t bRowB = (uint32_t)(warpCol * 64 + ((grp >> 1) << 3) + (lane & 7));
    uint32_t bKof = (uint32_t)((grp & 1) * 16);

    for (int c = 0; c < NCH; c++) {
        uint32_t sA = sbase + (uint32_t)(c % NSTG) * STGB;
        uint32_t sB = sA + A_BYTES;
        if (c + 3 < NCH) asm volatile("cp.async.wait_group 2;" ::: "memory");
        else             asm volatile("cp.async.wait_group 0;" ::: "memory");
        __syncthreads();          // single barrier per chunk (4-stage ring)

        if (c + 3 < NCH)
            load_stage(sbase + (uint32_t)((c + 3) % NSTG) * STGB,
                       sbase + (uint32_t)((c + 3) % NSTG) * STGB + A_BYTES,
                       Ag, Bg, (c + 3) * BK, t);

        #pragma unroll
        for (int ks = 0; ks < 4; ks++) {
            uint32_t a[4][4], b[8][2];
            #pragma unroll
            for (int nfp = 0; nfp < 4; nfp++) {
                uint32_t addr = sB + (bRowB + nfp * 16) * 144u + ks * 32u + bKof;
                ldm_x4(b[2 * nfp][0], b[2 * nfp][1], b[2 * nfp + 1][0], b[2 * nfp + 1][1], addr);
            }
            #pragma unroll
            for (int mf = 0; mf < 4; mf++) {
                uint32_t addr = sA + (aRow + mf * 16) * 144u + ks * 32u + aKof;
                ldm_x4(a[mf][0], a[mf][1], a[mf][2], a[mf][3], addr);
            }
            #pragma unroll
            for (int mf = 0; mf < 4; mf++)
                #pragma unroll
                for (int nf = 0; nf < 8; nf++)
                    mma_bf16(acc[mf][nf], a[mf][0], a[mf][1], a[mf][2], a[mf][3],
                             b[nf][0], b[nf][1]);
        }
    }

    // epilogue: S = sq_i + sq_j - 2G, softplus over strict upper triangle
    int g = lane >> 2, tg = lane & 3;
    float sqj[8][2];
    int jc[8];
    #pragma unroll
    for (int nf = 0; nf < 8; nf++) {
        int jl = warpCol * 64 + nf * 8 + 2 * tg;
        jc[nf] = jBase + jl;
        sqj[nf][0] = sqj_sh[jl];
        sqj[nf][1] = sqj_sh[jl + 1];
    }

    float lsum = 0.f;
    #pragma unroll
    for (int mf = 0; mf < 4; mf++) {
        int il = warpRow * 64 + mf * 16 + g;
        int i0 = iBase + il;
        float sqi0 = sqi_sh[il], sqi1 = sqi_sh[il + 8];
        #pragma unroll
        for (int nf = 0; nf < 8; nf++) {
            int j0 = jc[nf];
            float S;
            if (i0 < j0) {
                S = sqi0 + sqj[nf][0] - 2.f * acc[mf][nf][0];
                lsum += fmaxf(S, 0.f) + __logf(1.f + __expf(-fabsf(S)));
            }
            if (i0 < j0 + 1) {
                S = sqi0 + sqj[nf][1] - 2.f * acc[mf][nf][1];
                lsum += fmaxf(S, 0.f) + __logf(1.f + __expf(-fabsf(S)));
            }
            if (i0 + 8 < j0) {
                S = sqi1 + sqj[nf][0] - 2.f * acc[mf][nf][2];
                lsum += fmaxf(S, 0.f) + __logf(1.f + __expf(-fabsf(S)));
            }
            if (i0 + 8 < j0 + 1) {
                S = sqi1 + sqj[nf][1] - 2.f * acc[mf][nf][3];
                lsum += fmaxf(S, 0.f) + __logf(1.f + __expf(-fabsf(S)));
            }
        }
    }

    red[t] = lsum; __syncthreads();
    for (int off = 128; off > 0; off >>= 1) { if (t < off) red[t] += red[t + off]; __syncthreads(); }
    if (t == 0) {
        atomicAdd(&g_pairsum, (double)red[0]);
        __threadfence();
        int prev = atomicAdd(&g_done, 1);
        if (prev == NTILES - 1) {          // last block: finalize
            double ts = 0.0;
            for (int k = 0; k < NCLS; k++)
                ts += (double)(2.f * (float)g_counts[k] * g_P[k] - 2.f * g_wss[k]);
            double denom = (double)NPTS * (double)(NPTS - 1);
            out[0] = (float)((2.0 * g_pairsum - ts) / denom);
        }
    }
}

// ------------------------------------------------------------------
extern "C" void kernel_launch(void* const* d_in, const int* in_sizes, int n_in,
                              void* d_out, int out_size) {
    const float* X   = (const float*)d_in[0];
    const int*   tgt = (const int*)d_in[1];
    float*       out = (float*)d_out;
    (void)in_sizes; (void)n_in; (void)out_size;

    cudaFuncSetAttribute(k_main, cudaFuncAttributeMaxDynamicSharedMemorySize, DSMEM_BYTES);

    k_init<<<1, 1024>>>(tgt);
    k_phase1<<<dim3(NDCH, RCH), 64>>>(X, tgt);
    k_reduce_w<<<DIMS, 256>>>();
    k_xwsq<<<NPTS, 256>>>(X, tgt);
    k_main<<<NTILES, 256, DSMEM_BYTES>>>(out);
}

// round 16
// speedup vs baseline: 1.0084x; 1.0084x over previous
#include <cuda_runtime.h>
#include <cuda_bf16.h>
#include <cstdint>

#define NPTS 4096
#define DIMS 1024
#define NCLS 64
#define EPSV 0.1f

#define RCH  32                 // row chunks for phase-1 partials
#define RPC  (NPTS / RCH)       // 128 rows per chunk
#define DCH  64                 // dims per phase-1 block
#define NDCH (DIMS / DCH)       // 16

// k_main tiling (bf16 mma.sync m16n8k16)
#define BM   256
#define BN   128
#define BK   64                 // bf16 elems per chunk = 128 B per row
#define NCH  (DIMS / BK)        // 16 chunks
#define NTILES 272              // triangle tiles: sum_{bi<16} (32 - 2*bi)
#define LSTRH 72                // smem row stride in halfs (144 B)
#define A_BYTES (BM * LSTRH * 2)   // 36864
#define B_BYTES (BN * LSTRH * 2)   // 18432
#define STGB  (A_BYTES + B_BYTES)  // 55296 B per stage
#define NSTG  4
#define DSMEM_BYTES (NSTG * STGB)  // 221184 B

// ---- static device scratch (no allocations allowed) ----
__device__ int      g_counts[NCLS];
__device__ float    g_spart[DIMS][RCH][NCLS];   // 8 MB partials, contiguous per dim
__device__ float    g_Apart[RCH][DIMS];
__device__ float    g_Qpart[RCH][DIMS];
__device__ float    g_s[NCLS][DIMS];
__device__ float    g_w[DIMS];
__device__ unsigned short g_xh[(size_t)NPTS * DIMS];   // bf16(x)
__device__ unsigned short g_xwh[(size_t)NPTS * DIMS];  // bf16(w*x)
__device__ float    g_sq[NPTS];                 // sq_i = sum_d w_d x_id^2 (fp32 exact)
__device__ float    g_P[NCLS];
__device__ float    g_wss[NCLS];
__device__ double   g_pairsum;
__device__ int      g_done;

// ---------------- helpers ----------------
__device__ __forceinline__ uint32_t smem_u32(const void* p) {
    uint32_t a;
    asm("{ .reg .u64 t; cvta.to.shared.u64 t, %1; cvt.u32.u64 %0, t; }" : "=r"(a) : "l"(p));
    return a;
}
__device__ __forceinline__ void cp16(uint32_t dst, const void* src) {
    asm volatile("cp.async.cg.shared.global [%0], [%1], 16;" :: "r"(dst), "l"(src) : "memory");
}
__device__ __forceinline__ void ldm_x4(uint32_t& r0, uint32_t& r1, uint32_t& r2, uint32_t& r3,
                                       uint32_t addr) {
    asm volatile("ldmatrix.sync.aligned.m8n8.x4.shared.b16 {%0,%1,%2,%3}, [%4];"
                 : "=r"(r0), "=r"(r1), "=r"(r2), "=r"(r3) : "r"(addr));
}
__device__ __forceinline__ void mma_bf16(float* c, uint32_t a0, uint32_t a1, uint32_t a2,
                                         uint32_t a3, uint32_t b0, uint32_t b1) {
    asm volatile("mma.sync.aligned.m16n8k16.row.col.f32.bf16.bf16.f32 "
                 "{%0,%1,%2,%3}, {%4,%5,%6,%7}, {%8,%9}, {%0,%1,%2,%3};"
                 : "+f"(c[0]), "+f"(c[1]), "+f"(c[2]), "+f"(c[3])
                 : "r"(a0), "r"(a1), "r"(a2), "r"(a3), "r"(b0), "r"(b1));
}

// ------------------------------------------------------------------
// Fused init + class histogram (single block).
__global__ void k_init(const int* __restrict__ tgt) {
    __shared__ int hist[NCLS];
    int t = threadIdx.x;                 // 1024 threads
    if (t < NCLS) { hist[t] = 0; g_P[t] = 0.f; g_wss[t] = 0.f; }
    if (t == NCLS) { g_pairsum = 0.0; g_done = 0; }
    __syncthreads();
    #pragma unroll
    for (int i = t; i < NPTS; i += 1024) atomicAdd(&hist[tgt[i]], 1);
    __syncthreads();
    if (t < NCLS) g_counts[t] = hist[t];
}

__global__ void k_phase1(const float* __restrict__ X, const int* __restrict__ tgt) {
    __shared__ float s_sh[NCLS * DCH];
    __shared__ float cnt_sh[NCLS];
    __shared__ int   tg_sh[RPC];
    int t  = threadIdx.x;                // 0..63
    int dc = blockIdx.x, rc = blockIdx.y;

    for (int i = t; i < NCLS * DCH; i += 64) s_sh[i] = 0.f;
    cnt_sh[t] = (float)g_counts[t];
    for (int r = t; r < RPC; r += 64) tg_sh[r] = tgt[rc * RPC + r];
    __syncthreads();

    const float* xp = X + (size_t)(rc * RPC) * DIMS + dc * DCH + t;
    float aacc = 0.f, qacc = 0.f;
    #pragma unroll 8
    for (int r = 0; r < RPC; r++) {
        float v = xp[(size_t)r * DIMS];
        int   k = tg_sh[r];
        s_sh[k * DCH + t] += v;
        float v2 = v * v;
        qacc += v2;
        aacc = fmaf(cnt_sh[k], v2, aacc);
    }
    __syncthreads();

    int d = dc * DCH + t;
    #pragma unroll
    for (int k4 = 0; k4 < NCLS; k4 += 4) {
        float4 v = make_float4(s_sh[(k4 + 0) * DCH + t], s_sh[(k4 + 1) * DCH + t],
                               s_sh[(k4 + 2) * DCH + t], s_sh[(k4 + 3) * DCH + t]);
        *(float4*)&g_spart[d][rc][k4] = v;
    }
    g_Apart[rc][d] = aacc;
    g_Qpart[rc][d] = qacc;
}

// 256 threads: block d streams its contiguous 8KB partial slab, computes w_d,
// and folds the wss contribution (atomicAdd per class).
__global__ void k_reduce_w() {
    int d = blockIdx.x, t = threadIdx.x;
    int k = t & 63, rg = t >> 6;         // class, rc-group (4 groups x 8 rc)

    float s = 0.f;
    #pragma unroll
    for (int rc = rg * 8; rc < rg * 8 + 8; rc++) s += g_spart[d][rc][k];
    __shared__ float sp[4][NCLS];
    sp[rg][k] = s;
    __syncthreads();

    __shared__ float sh1[NCLS], sh2[NCLS], sh3[NCLS], sh4[NCLS], sh5[NCLS];
    __shared__ float s_k[NCLS];
    __shared__ float s_wd;
    if (rg == 0) {
        s = sp[0][k] + sp[1][k] + sp[2][k] + sp[3][k];
        g_s[k][d] = s;
        s_k[k] = s;
        float c = (float)g_counts[k];
        sh1[k] = s * s; sh2[k] = s; sh3[k] = c * c;
        sh4[k] = (k < RCH) ? g_Apart[k][d] : 0.f;   // thread k doubles as rc=k
        sh5[k] = (k < RCH) ? g_Qpart[k][d] : 0.f;
    }
    __syncthreads();
    for (int off = 32; off > 0; off >>= 1) {
        if (t < off) {
            sh1[t] += sh1[t + off]; sh2[t] += sh2[t + off]; sh3[t] += sh3[t + off];
            sh4[t] += sh4[t + off]; sh5[t] += sh5[t + off];
        }
        __syncthreads();
    }

    if (t == 0) {
        float ssum2 = sh1[0], stot = sh2[0], sumc2 = sh3[0];
        float a = sh4[0], q = sh5[0];
        float cntpos = sumc2 - (float)NPTS;
        float cntneg = (float)NPTS * (float)NPTS - sumc2;
        float sum_pos = 2.f * a - 2.f * ssum2;
        float sum_neg = 2.f * (float)NPTS * q - 2.f * a - 2.f * stot * stot + 2.f * ssum2;
        s_wd = cntneg / (sum_neg + EPSV) - cntpos / (sum_pos + EPSV);
        g_w[d] = s_wd;
    }
    __syncthreads();
    if (t < NCLS) {                      // fused wss: wss_k += w_d * s_kd^2
        float s0 = s_k[t];
        atomicAdd(&g_wss[t], s_wd * s0 * s0);
    }
}

// xh = bf16(x), xwh = bf16(w*x), sq_i = sum w x^2 (fp32), P_k += sq_i
__global__ void k_xwsq(const float* __restrict__ X, const int* __restrict__ tgt) {
    int i = blockIdx.x, t = threadIdx.x;   // 256 threads, 4 dims each
    int lane = t & 31, w = t >> 5;
    const float4* xr = (const float4*)(X + (size_t)i * DIMS);
    const float4* wr = (const float4*)g_w;
    float4 x4 = xr[t], w4 = wr[t], o;
    o.x = x4.x * w4.x; o.y = x4.y * w4.y; o.z = x4.z * w4.z; o.w = x4.w * w4.w;
    float acc = x4.x * o.x + x4.y * o.y + x4.z * o.z + x4.w * o.w;

    __nv_bfloat162 hx0 = __floats2bfloat162_rn(x4.x, x4.y);
    __nv_bfloat162 hx1 = __floats2bfloat162_rn(x4.z, x4.w);
    __nv_bfloat162 ho0 = __floats2bfloat162_rn(o.x, o.y);
    __nv_bfloat162 ho1 = __floats2bfloat162_rn(o.z, o.w);
    uint2* dxh  = (uint2*)(g_xh  + (size_t)i * DIMS);
    uint2* dxwh = (uint2*)(g_xwh + (size_t)i * DIMS);
    uint2 px, po;
    px.x = *(uint32_t*)&hx0; px.y = *(uint32_t*)&hx1;
    po.x = *(uint32_t*)&ho0; po.y = *(uint32_t*)&ho1;
    dxh[t] = px; dxwh[t] = po;

    // warp shuffle reduction, then 8 partials via smem (single sync)
    #pragma unroll
    for (int off = 16; off > 0; off >>= 1)
        acc += __shfl_down_sync(0xffffffffu, acc, off);
    __shared__ float wsum[8];
    if (lane == 0) wsum[w] = acc;
    __syncthreads();
    if (t == 0) {
        float s = wsum[0] + wsum[1] + wsum[2] + wsum[3]
                + wsum[4] + wsum[5] + wsum[6] + wsum[7];
        g_sq[i] = s;
        atomicAdd(&g_P[tgt[i]], s);
    }
}

// ------------------------------------------------------------------
// bf16 mma.sync fused Gram + softplus. 256x128 tile, BK=64, 4-stage cp.async
// (one __syncthreads per chunk), ldmatrix.x4 fragments, 8 warps (4m x 2n).
// Last finishing block computes the final loss with PARALLEL loads.
__device__ __forceinline__ void load_stage(uint32_t sA, uint32_t sB,
                                           const unsigned short* Ag,
                                           const unsigned short* Bg,
                                           int kt, int t) {
    int seg = t & 7;               // 16B segment within 128B row
    int r0  = t >> 3;              // 32 rows per pass
    #pragma unroll
    for (int p = 0; p < 8; p++) {  // A: 256 rows
        int row = r0 + 32 * p;
        cp16(sA + row * 144u + seg * 16u, Ag + (size_t)row * DIMS + kt + seg * 8);
    }
    #pragma unroll
    for (int p = 0; p < 4; p++) {  // B: 128 rows
        int row = r0 + 32 * p;
        cp16(sB + row * 144u + seg * 16u, Bg + (size_t)row * DIMS + kt + seg * 8);
    }
    asm volatile("cp.async.commit_group;" ::: "memory");
}

__global__ void __launch_bounds__(256) k_main(float* __restrict__ out) {
    // map linear block id -> (bi, bj) on the triangle bj >= 2*bi
    int L = blockIdx.x, bi = 0, cnt = 32;
    while (L >= cnt) { L -= cnt; bi++; cnt -= 2; }
    int bj = 2 * bi + L;
    int iBase = bi * BM, jBase = bj * BN;

    extern __shared__ char dsmem[];
    __shared__ float red[256];
    __shared__ float sqi_sh[BM];
    __shared__ float sqj_sh[BN];
    __shared__ int   s_last;

    int t = threadIdx.x;
    int lane = t & 31, w = t >> 5;
    int warpRow = w & 3, warpCol = w >> 2;    // 4 x 2 warps
    uint32_t sbase = smem_u32(dsmem);

    const unsigned short* Ag = g_xh  + (size_t)iBase * DIMS;
    const unsigned short* Bg = g_xwh + (size_t)jBase * DIMS;

    // prefetch sq rows/cols for the epilogue
    sqi_sh[t] = g_sq[iBase + t];
    if (t < BN) sqj_sh[t] = g_sq[jBase + t];
    if (t == 0) s_last = 0;

    float acc[4][8][4];
    #pragma unroll
    for (int mf = 0; mf < 4; mf++)
        #pragma unroll
        for (int nf = 0; nf < 8; nf++)
            #pragma unroll
            for (int q = 0; q < 4; q++) acc[mf][nf][q] = 0.f;

    // prologue: chunks 0..2 into stages 0..2
    load_stage(sbase,            sbase + A_BYTES,            Ag, Bg, 0,      t);
    load_stage(sbase + STGB,     sbase + STGB + A_BYTES,     Ag, Bg, BK,     t);
    load_stage(sbase + 2 * STGB, sbase + 2 * STGB + A_BYTES, Ag, Bg, 2 * BK, t);

    // precomputed fragment address components
    uint32_t aRow = (uint32_t)(warpRow * 64 + (lane & 15));
    uint32_t aKof = (uint32_t)((lane >> 4) * 16);
    int grp = lane >> 3;
    uint32_t bRowB = (uint32_t)(warpCol * 64 + ((grp >> 1) << 3) + (lane & 7));
    uint32_t bKof = (uint32_t)((grp & 1) * 16);

    for (int c = 0; c < NCH; c++) {
        uint32_t sA = sbase + (uint32_t)(c % NSTG) * STGB;
        uint32_t sB = sA + A_BYTES;
        if (c + 3 < NCH) asm volatile("cp.async.wait_group 2;" ::: "memory");
        else             asm volatile("cp.async.wait_group 0;" ::: "memory");
        __syncthreads();          // single barrier per chunk (4-stage ring)

        if (c + 3 < NCH)
            load_stage(sbase + (uint32_t)((c + 3) % NSTG) * STGB,
                       sbase + (uint32_t)((c + 3) % NSTG) * STGB + A_BYTES,
                       Ag, Bg, (c + 3) * BK, t);

        #pragma unroll
        for (int ks = 0; ks < 4; ks++) {
            uint32_t a[4][4], b[8][2];
            #pragma unroll
            for (int nfp = 0; nfp < 4; nfp++) {
                uint32_t addr = sB + (bRowB + nfp * 16) * 144u + ks * 32u + bKof;
                ldm_x4(b[2 * nfp][0], b[2 * nfp][1], b[2 * nfp + 1][0], b[2 * nfp + 1][1], addr);
            }
            #pragma unroll
            for (int mf = 0; mf < 4; mf++) {
                uint32_t addr = sA + (aRow + mf * 16) * 144u + ks * 32u + aKof;
                ldm_x4(a[mf][0], a[mf][1], a[mf][2], a[mf][3], addr);
            }
            #pragma unroll
            for (int mf = 0; mf < 4; mf++)
                #pragma unroll
                for (int nf = 0; nf < 8; nf++)
                    mma_bf16(acc[mf][nf], a[mf][0], a[mf][1], a[mf][2], a[mf][3],
                             b[nf][0], b[nf][1]);
        }
    }

    // epilogue: S = sq_i + sq_j - 2G, softplus over strict upper triangle
    int g = lane >> 2, tg = lane & 3;
    float sqj[8][2];
    int jc[8];
    #pragma unroll
    for (int nf = 0; nf < 8; nf++) {
        int jl = warpCol * 64 + nf * 8 + 2 * tg;
        jc[nf] = jBase + jl;
        sqj[nf][0] = sqj_sh[jl];
        sqj[nf][1] = sqj_sh[jl + 1];
    }

    float lsum = 0.f;
    #pragma unroll
    for (int mf = 0; mf < 4; mf++) {
        int il = warpRow * 64 + mf * 16 + g;
        int i0 = iBase + il;
        float sqi0 = sqi_sh[il], sqi1 = sqi_sh[il + 8];
        #pragma unroll
        for (int nf = 0; nf < 8; nf++) {
            int j0 = jc[nf];
            float S;
            if (i0 < j0) {
                S = sqi0 + sqj[nf][0] - 2.f * acc[mf][nf][0];
                lsum += fmaxf(S, 0.f) + __logf(1.f + __expf(-fabsf(S)));
            }
            if (i0 < j0 + 1) {
                S = sqi0 + sqj[nf][1] - 2.f * acc[mf][nf][1];
                lsum += fmaxf(S, 0.f) + __logf(1.f + __expf(-fabsf(S)));
            }
            if (i0 + 8 < j0) {
                S = sqi1 + sqj[nf][0] - 2.f * acc[mf][nf][2];
                lsum += fmaxf(S, 0.f) + __logf(1.f + __expf(-fabsf(S)));
            }
            if (i0 + 8 < j0 + 1) {
                S = sqi1 + sqj[nf][1] - 2.f * acc[mf][nf][3];
                lsum += fmaxf(S, 0.f) + __logf(1.f + __expf(-fabsf(S)));
            }
        }
    }

    red[t] = lsum; __syncthreads();
    for (int off = 128; off > 0; off >>= 1) { if (t < off) red[t] += red[t + off]; __syncthreads(); }
    if (t == 0) {
        atomicAdd(&g_pairsum, (double)red[0]);
        __threadfence();
        int prev = atomicAdd(&g_done, 1);
        if (prev == NTILES - 1) s_last = 1;   // this block finalizes
    }
    __syncthreads();
    if (s_last) {
        __threadfence();                      // acquire all pairsum adds
        // parallel loads of per-class terms
        red[t] = (t < NCLS)
                   ? (2.f * (float)g_counts[t] * g_P[t] - 2.f * g_wss[t]) : 0.f;
        __syncthreads();
        if (t == 0) {
            double ts = 0.0;
            #pragma unroll
            for (int k = 0; k < NCLS; k++) ts += (double)red[k];   // fast LDS
            double denom = (double)NPTS * (double)(NPTS - 1);
            out[0] = (float)((2.0 * g_pairsum - ts) / denom);
        }
    }
}

// ------------------------------------------------------------------
extern "C" void kernel_launch(void* const* d_in, const int* in_sizes, int n_in,
                              void* d_out, int out_size) {
    const float* X   = (const float*)d_in[0];
    const int*   tgt = (const int*)d_in[1];
    float*       out = (float*)d_out;
    (void)in_sizes; (void)n_in; (void)out_size;

    cudaFuncSetAttribute(k_main, cudaFuncAttributeMaxDynamicSharedMemorySize, DSMEM_BYTES);

    k_init<<<1, 1024>>>(tgt);
    k_phase1<<<dim3(NDCH, RCH), 64>>>(X, tgt);
    k_reduce_w<<<DIMS, 256>>>();
    k_xwsq<<<NPTS, 256>>>(X, tgt);
    k_main<<<NTILES, 256, DSMEM_BYTES>>>(out);
}